// round 16
// baseline (speedup 1.0000x reference)
#include <cuda_runtime.h>
#include <cstdint>

#define NB 512
#define ND 256
#define NC 10
#define NSL 4              // timeline slices per batch-pair
#define NBLK (256 * NSL)   // kband grid

// ---------------------------------------------------------------------------
// packed fp32x2 helpers
// ---------------------------------------------------------------------------
typedef unsigned long long ps_t;

__device__ __forceinline__ ps_t pk2(float lo, float hi) {
    ps_t o; asm("mov.b64 %0,{%1,%2};" : "=l"(o) : "f"(lo), "f"(hi)); return o;
}
__device__ __forceinline__ void up2(ps_t a, float& lo, float& hi) {
    asm("mov.b64 {%0,%1},%2;" : "=f"(lo), "=f"(hi) : "l"(a));
}
__device__ __forceinline__ ps_t fma2(ps_t a, ps_t b, ps_t c) {
    ps_t d; asm("fma.rn.f32x2 %0,%1,%2,%3;" : "=l"(d) : "l"(a), "l"(b), "l"(c)); return d;
}
__device__ __forceinline__ ps_t add2(ps_t a, ps_t b) {
    ps_t d; asm("add.rn.f32x2 %0,%1,%2;" : "=l"(d) : "l"(a), "l"(b)); return d;
}
__device__ __forceinline__ ps_t relu2(ps_t a) {   // 2x FMNMX (proven)
    float l, h; up2(a, l, h);
    return pk2(fmaxf(l, 0.f), fmaxf(h, 0.f));
}

// ---------------------------------------------------------------------------
// constant weights (bootstrap only; kband copies them to shared each block)
// ---------------------------------------------------------------------------
__constant__ ulonglong2 c_w1p[5];
__constant__ ulonglong2 c_b1p[5];
__constant__ ulonglong2 c_w2p[3][3][5];
__constant__ ps_t c_b2p;

__device__ ulonglong2 g_packv[56];
__device__ float g_part[NBLK * 4];
__device__ float g_rs2[NB * ND];        // [pair][i][hb]
__device__ float g_csh[NB * ND * 2];    // [pair][half][j][hb]
__device__ unsigned int g_ctr;

// ---------------------------------------------------------------------------
// Kernel 1: row/col sums. grid=1024: block = (batch, row-half), 256 threads.
// (R12-proven form; unchanged.)
// ---------------------------------------------------------------------------
__global__ void __launch_bounds__(256) ksums(const float* __restrict__ x,
                                             const float* __restrict__ w1,
                                             const float* __restrict__ b1,
                                             const float* __restrict__ w2,
                                             const float* __restrict__ b2) {
    const int bid = blockIdx.x;
    const int b = bid >> 1;          // batch
    const int h = bid & 1;           // row half
    const int t = threadIdx.x;
    const int w = t >> 5;
    const int l = t & 31;
    const int bi = b >> 1;           // pair
    const int hb = b & 1;            // lane within pair

    if (bid == 0) {   // weight packing into LDC.128-friendly layout
        if (t < 5) {
            g_packv[t]     = make_ulonglong2(pk2(w1[2 * t], w1[2 * t]),
                                             pk2(w1[2 * t + 1], w1[2 * t + 1]));
            g_packv[5 + t] = make_ulonglong2(pk2(b1[2 * t], b1[2 * t]),
                                             pk2(b1[2 * t + 1], b1[2 * t + 1]));
        }
        if (t < 45) {
            const int e = t / 15, d = (t / 5) % 3, cc = t % 5;
            const float wa = w2[(2 * cc) * 9 + d * 3 + e];
            const float wb = w2[(2 * cc + 1) * 9 + d * 3 + e];
            g_packv[10 + t] = make_ulonglong2(pk2(wa, wa), pk2(wb, wb));
        }
        if (t == 0) g_packv[55] = make_ulonglong2(pk2(b2[0], b2[0]), 0ULL);
    }

    __shared__ float scs[8 * 256];
    const float4* __restrict__ xb =
        reinterpret_cast<const float4*>(x + (size_t)b * (ND * ND));

    float ca[8];
#pragma unroll
    for (int k = 0; k < 8; ++k) ca[k] = 0.f;

    const int i0 = 128 * h + 16 * w;
#pragma unroll 4
    for (int ri = 0; ri < 16; ++ri) {
        const int i = i0 + ri;
        float4 v0 = xb[i * 64 + 2 * l];
        float4 v1 = xb[i * 64 + 2 * l + 1];
        ca[0] += v0.x; ca[1] += v0.y; ca[2] += v0.z; ca[3] += v0.w;
        ca[4] += v1.x; ca[5] += v1.y; ca[6] += v1.z; ca[7] += v1.w;
        float rsum = (v0.x + v0.y) + (v0.z + v0.w) + (v1.x + v1.y) + (v1.z + v1.w);
#pragma unroll
        for (int o = 16; o; o >>= 1) rsum += __shfl_xor_sync(0xffffffffu, rsum, o);
        if (l == 0) g_rs2[bi * 512 + i * 2 + hb] = rsum;
    }
#pragma unroll
    for (int k = 0; k < 8; ++k) scs[w * 256 + 8 * l + k] = ca[k];
    __syncthreads();
    float c = 0.f;
#pragma unroll
    for (int ww = 0; ww < 8; ++ww) c += scs[ww * 256 + t];
    g_csh[((bi * 2 + h) * 256 + t) * 2 + hb] = c;
}

// ---------------------------------------------------------------------------
// tap: 10-ch generate + 3-row accumulate, weights via broadcast LDS.128
// (off the half-rate constant port; smem broadcast is conflict-free)
// ---------------------------------------------------------------------------
__device__ __forceinline__ void tapf(const ulonglong2* __restrict__ w1b1,
                                     const ulonglong2* __restrict__ w2e,
                                     ps_t tv, ps_t& A0, ps_t& A1, ps_t& A2) {
#pragma unroll
    for (int cc = 0; cc < 5; ++cc) {
        ulonglong2 wp = w1b1[2 * cc];
        ulonglong2 bp = w1b1[2 * cc + 1];
        ps_t ga = relu2(fma2(wp.x, tv, bp.x));
        ps_t gb = relu2(fma2(wp.y, tv, bp.y));
        ulonglong2 p0 = w2e[0 * 5 + cc];
        ulonglong2 p1 = w2e[1 * 5 + cc];
        ulonglong2 p2 = w2e[2 * 5 + cc];
        A0 = fma2(p0.x, ga, A0); A0 = fma2(p0.y, gb, A0);
        A1 = fma2(p1.x, ga, A1); A1 = fma2(p1.y, gb, A1);
        A2 = fma2(p2.x, ga, A2); A2 = fma2(p2.y, gb, A2);
    }
}

// ---------------------------------------------------------------------------
// peeled column sweep: guarded head, branch-free steady region, flush.
// Bias b2 folded into A1/pend1. Register cap prevents weight hoisting.
// ---------------------------------------------------------------------------
template <bool EDGE>
__device__ __forceinline__ void run_colp(
    int c, int pstart, int pbeg, int pend, int ef, bool addcorr, bool vm,
    ps_t csm, ps_t cs0, ps_t csp,
    const ps_t* __restrict__ srs, const ps_t (*__restrict__ sW)[4],
    const ulonglong2* __restrict__ sw1b1,
    const ulonglong2 (*__restrict__ sw2)[3][5],
    ps_t b2v, float c0, ps_t acc[4]) {

    ps_t wj[4];
#pragma unroll
    for (int k = 0; k < 4; ++k) wj[k] = sW[c][k];

    ps_t pend1 = b2v, a0last = 0ULL, ycol = 0ULL;

    // guarded head: warmup + band entry
    int gend = pend < c ? pend : c;
    {   int g2 = pbeg - 1;  if (g2 > gend) gend = g2; }
    if (gend > 255) gend = 255;

    int p = pstart;
    for (; p <= gend; ++p) {
        ps_t A0 = 0ULL, A1 = b2v, A2 = 0ULL;
        const ps_t rsp = srs[p];
        if ((!EDGE || vm) && p >= c - 1) tapf(sw1b1, &sw2[0][0][0], add2(rsp, csm), A0, A1, A2);
        if (p >= c)                      tapf(sw1b1, &sw2[1][0][0], add2(rsp, cs0), A0, A1, A2);
        if (p >= c + 1)                  tapf(sw1b1, &sw2[2][0][0], add2(rsp, csp), A0, A1, A2);
        if (p >= ef) {
            ps_t y = relu2(add2(pend1, A2));
            ps_t yc = (c <= p + 1) ? y : 0ULL;
            ycol = add2(ycol, yc);
            const ps_t* w4 = sW[p - 1];
#pragma unroll
            for (int k = 0; k < 4; ++k) acc[k] = fma2(yc, w4[k], acc[k]);
        }
        pend1 = add2(A1, a0last);
        a0last = A0;
    }

    // steady: all taps active, emit unmasked; no unroll (limits hoist scope)
    const int send = pend < 255 ? pend : 255;
#pragma unroll 1
    for (; p <= send; ++p) {
        ps_t A0 = 0ULL, A1 = b2v, A2 = 0ULL;
        const ps_t rsp = srs[p];
        if (!EDGE || vm) tapf(sw1b1, &sw2[0][0][0], add2(rsp, csm), A0, A1, A2);
        tapf(sw1b1, &sw2[1][0][0], add2(rsp, cs0), A0, A1, A2);
        tapf(sw1b1, &sw2[2][0][0], add2(rsp, csp), A0, A1, A2);

        ps_t y = relu2(add2(pend1, A2));
        ycol = add2(ycol, y);
        const ps_t* w4 = sW[p - 1];
#pragma unroll
        for (int k = 0; k < 4; ++k) acc[k] = fma2(y, w4[k], acc[k]);

        pend1 = add2(A1, a0last);
        a0last = A0;
    }

    // flush: p == 256 emits row 255 (taps contribute nothing; bias in pend1)
    if (pend == 256) {
        ps_t y = relu2(pend1);
        ycol = add2(ycol, y);
        const ps_t* w4 = sW[255];
#pragma unroll
        for (int k = 0; k < 4; ++k) acc[k] = fma2(y, w4[k], acc[k]);
    }

    if (addcorr) {
        const int rn = (253 - c) > 0 ? (253 - c) : 0;
        const int cn = (c - 2) > 0 ? (c - 2) : 0;
        const float cf = c0 * (float)(rn + cn);
        ycol = add2(ycol, pk2(cf, cf));
    }
#pragma unroll
    for (int k = 0; k < 4; ++k) acc[k] = fma2(ycol, wj[k], acc[k]);
}

// ---------------------------------------------------------------------------
// Kernel 2: band conv + fused fc1 + fused final fc2 (last-block reduction).
// grid = 1024 (= 256 pairs x 4 slices), 128 threads.
// __launch_bounds__(128, 6): R14-proven 85-reg budget — rematerializes the
// weight loads in-loop (now LDS, off the constant port) without spilling.
// ---------------------------------------------------------------------------
__global__ void __launch_bounds__(128, 6) kband(const float* __restrict__ fc1w,
                                                const float* __restrict__ fc1b,
                                                const float* __restrict__ fc2w,
                                                const float* __restrict__ fc2b,
                                                float* __restrict__ out) {
    const int bid = blockIdx.x;
    const int pair = bid >> 2;
    const int s = bid & 3;

    const int t = threadIdx.x;
    const int w = t >> 5;
    const int lane = t & 31;
    const int q = t;                 // low column of the pair (q, 255-q)

    __shared__ ps_t srs[ND];
    __shared__ ps_t scs[ND];
    __shared__ ps_t sW[ND][4];
    __shared__ ulonglong2 sw1b1[10];      // [cc] -> {w1 pair}, {b1 pair}
    __shared__ ulonglong2 sw2[3][3][5];   // [e][d][cc]
    __shared__ ps_t sred[4][4];
    __shared__ int lastf;

#pragma unroll
    for (int r = 0; r < 2; ++r) {
        const int i = t + 128 * r;
        srs[i] = ((const ps_t*)g_rs2)[pair * 256 + i];
        scs[i] = add2(((const ps_t*)g_csh)[(pair * 2 + 0) * 256 + i],
                      ((const ps_t*)g_csh)[(pair * 2 + 1) * 256 + i]);
    }
    if (t < 5) { sw1b1[2 * t] = c_w1p[t]; sw1b1[2 * t + 1] = c_b1p[t]; }
    if (t < 45) ((ulonglong2*)sw2)[t] = ((const ulonglong2*)c_w2p)[t];

    const int b0 = 2 * pair;
    for (int idx = t; idx < 1024; idx += 128) {
        const int i = idx >> 2, k = idx & 3;
        sW[i][k] = pk2(fc1w[(size_t)k * 131072 + b0 * 256 + i],
                       fc1w[(size_t)k * 131072 + (b0 + 1) * 256 + i]);
    }
    __syncthreads();

    const ps_t b2v = c_b2p;
    float b2f, b2d; up2(b2v, b2f, b2d);
    const float c0 = fmaxf(b2f, 0.f);

    ps_t acc[4] = {0ULL, 0ULL, 0ULL, 0ULL};
    const bool edge = (w == 0);

    // virtual timeline: part A = col q over p in [pA0, 256]; part B = col 255-q
    const int pA0 = (q - 3 > 0) ? (q - 3) : 0;
    const int iterA = 257 - pA0;
    const int iterB = q + 5;           // pB0 = 252 - q
    const int tot = iterA + iterB;
    const int v0 = (tot * s) >> 2;
    const int v1 = (tot * (s + 1)) >> 2;

    // ---- part A: column q ----
    {
        const int a0 = v0;
        const int a1 = (v1 < iterA) ? v1 : iterA;
        if (a0 < a1) {
            const int c = q;
            const int pbeg = pA0 + a0;
            const int pend = pA0 + a1 - 1;
            const int pstart = (a0 == 0) ? pbeg : ((pbeg - 2 > 0) ? pbeg - 2 : 0);
            const int ef = (pbeg > 1) ? pbeg : 1;
            const bool vm = (c >= 1);
            const ps_t csm = vm ? scs[c - 1] : 0ULL;
            const ps_t cs0v = scs[c];
            const ps_t csp = (c <= 254) ? scs[c + 1] : 0ULL;
            if (edge)
                run_colp<true >(c, pstart, pbeg, pend, ef, a0 == 0, vm,
                                csm, cs0v, csp, srs, sW, sw1b1, sw2, b2v, c0, acc);
            else
                run_colp<false>(c, pstart, pbeg, pend, ef, a0 == 0, vm,
                                csm, cs0v, csp, srs, sW, sw1b1, sw2, b2v, c0, acc);
        }
    }
    // ---- part B: column 255 - q ----
    {
        const int u0 = (v0 > iterA) ? (v0 - iterA) : 0;
        const int u1 = v1 - iterA;
        if (u1 > u0) {
            const int c = 255 - q;
            const int pB0 = 252 - q;
            const int pbeg = pB0 + u0;
            const int pend = pB0 + u1 - 1;
            const int pstart = (u0 == 0) ? pbeg : ((pbeg - 2 > 0) ? pbeg - 2 : 0);
            const int ef = (pbeg > 1) ? pbeg : 1;
            const bool vm = (c >= 1);
            const ps_t csm = vm ? scs[c - 1] : 0ULL;
            const ps_t cs0v = scs[c];
            const ps_t csp = (c <= 254) ? scs[c + 1] : 0ULL;
            if (edge)
                run_colp<true >(c, pstart, pbeg, pend, ef, u0 == 0, vm,
                                csm, cs0v, csp, srs, sW, sw1b1, sw2, b2v, c0, acc);
            else
                run_colp<false>(c, pstart, pbeg, pend, ef, u0 == 0, vm,
                                csm, cs0v, csp, srs, sW, sw1b1, sw2, b2v, c0, acc);
        }
    }

    // reduce acc across lanes, then across the 4 warps
#pragma unroll
    for (int k = 0; k < 4; ++k) {
#pragma unroll
        for (int o = 16; o; o >>= 1)
            acc[k] = add2(acc[k], __shfl_xor_sync(0xffffffffu, acc[k], o));
    }
    if (lane == 0) {
#pragma unroll
        for (int k = 0; k < 4; ++k) sred[w][k] = acc[k];
    }
    __syncthreads();
    if (t < 4) {
        ps_t sv = add2(add2(sred[0][t], sred[1][t]), add2(sred[2][t], sred[3][t]));
        float lo, hi; up2(sv, lo, hi);
        g_part[bid * 4 + t] = lo + hi;
    }

    // ------- last-block final reduction + fc2 -------
    __threadfence();
    __syncthreads();
    if (t == 0) {
        unsigned int o = atomicAdd(&g_ctr, 1u);
        lastf = (o == (unsigned)(NBLK - 1)) ? 1 : 0;
    }
    __syncthreads();
    if (lastf) {
        float sv = 0.f;
        for (int i = lane; i < NBLK; i += 32) sv += g_part[i * 4 + w];
#pragma unroll
        for (int o = 16; o; o >>= 1) sv += __shfl_xor_sync(0xffffffffu, sv, o);
        __shared__ float fsh[4];
        if (lane == 0) fsh[w] = sv;
        __syncthreads();
        if (t == 0) {
            float h0 = fmaxf(fsh[0] + fc1b[0], 0.f);
            float h1 = fmaxf(fsh[1] + fc1b[1], 0.f);
            float h2 = fmaxf(fsh[2] + fc1b[2], 0.f);
            float h3 = fmaxf(fsh[3] + fc1b[3], 0.f);
            out[0] = fc2w[0] * h0 + fc2w[1] * h1 + fc2w[2] * h2 + fc2w[3] * h3 + fc2b[0];
            out[1] = fc2w[4] * h0 + fc2w[5] * h1 + fc2w[6] * h2 + fc2w[7] * h3 + fc2b[1];
            g_ctr = 0;   // reset for next launch/replay
        }
    }
}

// ---------------------------------------------------------------------------
extern "C" void kernel_launch(void* const* d_in, const int* in_sizes, int n_in,
                              void* d_out, int out_size) {
    const float* x    = (const float*)d_in[0];
    const float* w1   = (const float*)d_in[1];
    const float* b1   = (const float*)d_in[2];
    const float* w2   = (const float*)d_in[3];
    const float* b2   = (const float*)d_in[4];
    const float* fc1w = (const float*)d_in[5];
    const float* fc1b = (const float*)d_in[6];
    const float* fc2w = (const float*)d_in[7];
    const float* fc2b = (const float*)d_in[8];

    ksums<<<2 * NB, 256>>>(x, w1, b1, w2, b2);

    void* gp = nullptr;
    cudaGetSymbolAddress(&gp, g_packv);
    cudaMemcpyToSymbolAsync(c_w1p, gp, 5 * sizeof(ulonglong2), 0,
                            cudaMemcpyDeviceToDevice, 0);
    cudaMemcpyToSymbolAsync(c_b1p, (char*)gp + 5 * sizeof(ulonglong2),
                            5 * sizeof(ulonglong2), 0, cudaMemcpyDeviceToDevice, 0);
    cudaMemcpyToSymbolAsync(c_w2p, (char*)gp + 10 * sizeof(ulonglong2),
                            45 * sizeof(ulonglong2), 0, cudaMemcpyDeviceToDevice, 0);
    cudaMemcpyToSymbolAsync(c_b2p, (char*)gp + 55 * sizeof(ulonglong2),
                            sizeof(ps_t), 0, cudaMemcpyDeviceToDevice, 0);

    kband<<<NBLK, 128>>>(fc1w, fc1b, fc2w, fc2b, (float*)d_out);
}

// round 17
// speedup vs baseline: 5.6763x; 5.6763x over previous
#include <cuda_runtime.h>
#include <cstdint>

#define NB 512
#define ND 256
#define NC 10
#define NSL 4              // timeline slices per batch-pair
#define NBLK (256 * NSL)   // kband grid

// ---------------------------------------------------------------------------
// packed fp32x2 helpers
// ---------------------------------------------------------------------------
typedef unsigned long long ps_t;

__device__ __forceinline__ ps_t pk2(float lo, float hi) {
    ps_t o; asm("mov.b64 %0,{%1,%2};" : "=l"(o) : "f"(lo), "f"(hi)); return o;
}
__device__ __forceinline__ void up2(ps_t a, float& lo, float& hi) {
    asm("mov.b64 {%0,%1},%2;" : "=f"(lo), "=f"(hi) : "l"(a));
}
__device__ __forceinline__ ps_t fma2(ps_t a, ps_t b, ps_t c) {
    ps_t d; asm("fma.rn.f32x2 %0,%1,%2,%3;" : "=l"(d) : "l"(a), "l"(b), "l"(c)); return d;
}
__device__ __forceinline__ ps_t add2(ps_t a, ps_t b) {
    ps_t d; asm("add.rn.f32x2 %0,%1,%2;" : "=l"(d) : "l"(a), "l"(b)); return d;
}
__device__ __forceinline__ ps_t relu2(ps_t a) {   // 2x FMNMX (proven)
    float l, h; up2(a, l, h);
    return pk2(fmaxf(l, 0.f), fmaxf(h, 0.f));
}

// ---------------------------------------------------------------------------
// constant weights, LDC.128 layout (channel-pair vectors) — R12/R14-proven
// ---------------------------------------------------------------------------
__constant__ ulonglong2 c_w1p[5];
__constant__ ulonglong2 c_b1p[5];
__constant__ ulonglong2 c_w2p[3][3][5];
__constant__ ps_t c_b2p;

__device__ ulonglong2 g_packv[56];
__device__ float g_part[NBLK * 4];
__device__ float g_rs2[NB * ND];            // [pair][i][hb]
__device__ float g_csq[NB * ND * 4];        // [pair][quarter][j][hb]
__device__ unsigned int g_ctr;

// ---------------------------------------------------------------------------
// Kernel 1: row/col sums. grid=2048: block = (batch, row-QUARTER), 256 thr.
// Quarter split doubles resident blocks vs R14 (more outstanding LDGs).
// Col sums written as per-quarter partials (combined in kband preload).
// ---------------------------------------------------------------------------
__global__ void __launch_bounds__(256) ksums(const float* __restrict__ x,
                                             const float* __restrict__ w1,
                                             const float* __restrict__ b1,
                                             const float* __restrict__ w2,
                                             const float* __restrict__ b2) {
    const int bid = blockIdx.x;
    const int b = bid >> 2;          // batch
    const int h = bid & 3;           // row quarter
    const int t = threadIdx.x;
    const int w = t >> 5;
    const int l = t & 31;
    const int bi = b >> 1;           // pair
    const int hb = b & 1;            // lane within pair

    if (bid == 0) {   // weight packing into LDC.128-friendly layout
        if (t < 5) {
            g_packv[t]     = make_ulonglong2(pk2(w1[2 * t], w1[2 * t]),
                                             pk2(w1[2 * t + 1], w1[2 * t + 1]));
            g_packv[5 + t] = make_ulonglong2(pk2(b1[2 * t], b1[2 * t]),
                                             pk2(b1[2 * t + 1], b1[2 * t + 1]));
        }
        if (t < 45) {
            const int e = t / 15, d = (t / 5) % 3, cc = t % 5;
            const float wa = w2[(2 * cc) * 9 + d * 3 + e];
            const float wb = w2[(2 * cc + 1) * 9 + d * 3 + e];
            g_packv[10 + t] = make_ulonglong2(pk2(wa, wa), pk2(wb, wb));
        }
        if (t == 0) g_packv[55] = make_ulonglong2(pk2(b2[0], b2[0]), 0ULL);
    }

    __shared__ float scs[8 * 256];
    const float4* __restrict__ xb =
        reinterpret_cast<const float4*>(x + (size_t)b * (ND * ND));

    float ca[8];
#pragma unroll
    for (int k = 0; k < 8; ++k) ca[k] = 0.f;

    const int i0 = 64 * h + 8 * w;
#pragma unroll 4
    for (int ri = 0; ri < 8; ++ri) {
        const int i = i0 + ri;
        float4 v0 = xb[i * 64 + 2 * l];
        float4 v1 = xb[i * 64 + 2 * l + 1];
        ca[0] += v0.x; ca[1] += v0.y; ca[2] += v0.z; ca[3] += v0.w;
        ca[4] += v1.x; ca[5] += v1.y; ca[6] += v1.z; ca[7] += v1.w;
        float rsum = (v0.x + v0.y) + (v0.z + v0.w) + (v1.x + v1.y) + (v1.z + v1.w);
#pragma unroll
        for (int o = 16; o; o >>= 1) rsum += __shfl_xor_sync(0xffffffffu, rsum, o);
        if (l == 0) g_rs2[bi * 512 + i * 2 + hb] = rsum;
    }
#pragma unroll
    for (int k = 0; k < 8; ++k) scs[w * 256 + 8 * l + k] = ca[k];
    __syncthreads();
    float c = 0.f;
#pragma unroll
    for (int ww = 0; ww < 8; ++ww) c += scs[ww * 256 + t];
    g_csq[((bi * 4 + h) * 256 + t) * 2 + hb] = c;
}

// ---------------------------------------------------------------------------
// tap: 10-ch generate + 3-row accumulate, weights via LDC.128 pairs
// ---------------------------------------------------------------------------
__device__ __forceinline__ void tap2(ps_t tv, int e, ps_t& A0, ps_t& A1, ps_t& A2) {
#pragma unroll
    for (int cc = 0; cc < 5; ++cc) {
        ulonglong2 wp = c_w1p[cc];
        ulonglong2 bp = c_b1p[cc];
        ps_t ga = relu2(fma2(wp.x, tv, bp.x));
        ps_t gb = relu2(fma2(wp.y, tv, bp.y));
        ulonglong2 p0 = c_w2p[e][0][cc];
        ulonglong2 p1 = c_w2p[e][1][cc];
        ulonglong2 p2 = c_w2p[e][2][cc];
        A0 = fma2(p0.x, ga, A0); A0 = fma2(p0.y, gb, A0);
        A1 = fma2(p1.x, ga, A1); A1 = fma2(p1.y, gb, A1);
        A2 = fma2(p2.x, ga, A2); A2 = fma2(p2.y, gb, A2);
    }
}

// ---------------------------------------------------------------------------
// peeled column sweep (R14-proven): guarded head, branch-free steady, flush.
// Bias b2 folded into A1/pend1. Register cap prevents constant hoisting.
// ---------------------------------------------------------------------------
template <bool EDGE>
__device__ __forceinline__ void run_colp(
    int c, int pstart, int pbeg, int pend, int ef, bool addcorr, bool vm,
    ps_t csm, ps_t cs0, ps_t csp,
    const ps_t* __restrict__ srs, const ps_t (*__restrict__ sW)[4],
    ps_t b2v, float c0, ps_t acc[4]) {

    ps_t wj[4];
#pragma unroll
    for (int k = 0; k < 4; ++k) wj[k] = sW[c][k];

    ps_t pend1 = b2v, a0last = 0ULL, ycol = 0ULL;

    // guarded head: warmup + band entry
    int gend = pend < c ? pend : c;
    {   int g2 = pbeg - 1;  if (g2 > gend) gend = g2; }
    if (gend > 255) gend = 255;

    int p = pstart;
    for (; p <= gend; ++p) {
        ps_t A0 = 0ULL, A1 = b2v, A2 = 0ULL;
        const ps_t rsp = srs[p];
        if ((!EDGE || vm) && p >= c - 1) tap2(add2(rsp, csm), 0, A0, A1, A2);
        if (p >= c)                      tap2(add2(rsp, cs0), 1, A0, A1, A2);
        if (p >= c + 1)                  tap2(add2(rsp, csp), 2, A0, A1, A2);
        if (p >= ef) {
            ps_t y = relu2(add2(pend1, A2));
            ps_t yc = (c <= p + 1) ? y : 0ULL;
            ycol = add2(ycol, yc);
            const ps_t* w4 = sW[p - 1];
#pragma unroll
            for (int k = 0; k < 4; ++k) acc[k] = fma2(yc, w4[k], acc[k]);
        }
        pend1 = add2(A1, a0last);
        a0last = A0;
    }

    // steady: all taps active, emit unmasked; no unroll (limits hoist scope)
    const int send = pend < 255 ? pend : 255;
#pragma unroll 1
    for (; p <= send; ++p) {
        ps_t A0 = 0ULL, A1 = b2v, A2 = 0ULL;
        const ps_t rsp = srs[p];
        if (!EDGE || vm) tap2(add2(rsp, csm), 0, A0, A1, A2);
        tap2(add2(rsp, cs0), 1, A0, A1, A2);
        tap2(add2(rsp, csp), 2, A0, A1, A2);

        ps_t y = relu2(add2(pend1, A2));
        ycol = add2(ycol, y);
        const ps_t* w4 = sW[p - 1];
#pragma unroll
        for (int k = 0; k < 4; ++k) acc[k] = fma2(y, w4[k], acc[k]);

        pend1 = add2(A1, a0last);
        a0last = A0;
    }

    // flush: p == 256 emits row 255 (taps contribute nothing; bias in pend1)
    if (pend == 256) {
        ps_t y = relu2(pend1);
        ycol = add2(ycol, y);
        const ps_t* w4 = sW[255];
#pragma unroll
        for (int k = 0; k < 4; ++k) acc[k] = fma2(y, w4[k], acc[k]);
    }

    if (addcorr) {
        const int rn = (253 - c) > 0 ? (253 - c) : 0;
        const int cn = (c - 2) > 0 ? (c - 2) : 0;
        const float cf = c0 * (float)(rn + cn);
        ycol = add2(ycol, pk2(cf, cf));
    }
#pragma unroll
    for (int k = 0; k < 4; ++k) acc[k] = fma2(ycol, wj[k], acc[k]);
}

// ---------------------------------------------------------------------------
// Kernel 2: band conv + fused fc1 + fused final fc2 (last-block reduction).
// grid = 1024 (= 256 pairs x 4 slices), 128 threads.
// __launch_bounds__(128, 6): the R14-proven optimum (85-reg budget,
// rematerialize-not-spill, no hoist blow-up).
// ---------------------------------------------------------------------------
__global__ void __launch_bounds__(128, 6) kband(const float* __restrict__ fc1w,
                                                const float* __restrict__ fc1b,
                                                const float* __restrict__ fc2w,
                                                const float* __restrict__ fc2b,
                                                float* __restrict__ out) {
    const int bid = blockIdx.x;
    const int pair = bid >> 2;
    const int s = bid & 3;

    const int t = threadIdx.x;
    const int w = t >> 5;
    const int lane = t & 31;
    const int q = t;                 // low column of the pair (q, 255-q)

    __shared__ ps_t srs[ND];
    __shared__ ps_t scs[ND];
    __shared__ ps_t sW[ND][4];
    __shared__ ps_t sred[4][4];
    __shared__ int lastf;

#pragma unroll
    for (int r = 0; r < 2; ++r) {
        const int i = t + 128 * r;
        srs[i] = ((const ps_t*)g_rs2)[pair * 256 + i];
        scs[i] = add2(add2(((const ps_t*)g_csq)[(pair * 4 + 0) * 256 + i],
                           ((const ps_t*)g_csq)[(pair * 4 + 1) * 256 + i]),
                      add2(((const ps_t*)g_csq)[(pair * 4 + 2) * 256 + i],
                           ((const ps_t*)g_csq)[(pair * 4 + 3) * 256 + i]));
    }
    const int b0 = 2 * pair;
    for (int idx = t; idx < 1024; idx += 128) {
        const int i = idx >> 2, k = idx & 3;
        sW[i][k] = pk2(fc1w[(size_t)k * 131072 + b0 * 256 + i],
                       fc1w[(size_t)k * 131072 + (b0 + 1) * 256 + i]);
    }
    __syncthreads();

    const ps_t b2v = c_b2p;
    float b2f, b2d; up2(b2v, b2f, b2d);
    const float c0 = fmaxf(b2f, 0.f);

    ps_t acc[4] = {0ULL, 0ULL, 0ULL, 0ULL};
    const bool edge = (w == 0);

    // virtual timeline: part A = col q over p in [pA0, 256]; part B = col 255-q
    const int pA0 = (q - 3 > 0) ? (q - 3) : 0;
    const int iterA = 257 - pA0;
    const int iterB = q + 5;           // pB0 = 252 - q
    const int tot = iterA + iterB;
    const int v0 = (tot * s) >> 2;
    const int v1 = (tot * (s + 1)) >> 2;

    // ---- part A: column q ----
    {
        const int a0 = v0;
        const int a1 = (v1 < iterA) ? v1 : iterA;
        if (a0 < a1) {
            const int c = q;
            const int pbeg = pA0 + a0;
            const int pend = pA0 + a1 - 1;
            const int pstart = (a0 == 0) ? pbeg : ((pbeg - 2 > 0) ? pbeg - 2 : 0);
            const int ef = (pbeg > 1) ? pbeg : 1;
            const bool vm = (c >= 1);
            const ps_t csm = vm ? scs[c - 1] : 0ULL;
            const ps_t cs0v = scs[c];
            const ps_t csp = (c <= 254) ? scs[c + 1] : 0ULL;
            if (edge)
                run_colp<true >(c, pstart, pbeg, pend, ef, a0 == 0, vm,
                                csm, cs0v, csp, srs, sW, b2v, c0, acc);
            else
                run_colp<false>(c, pstart, pbeg, pend, ef, a0 == 0, vm,
                                csm, cs0v, csp, srs, sW, b2v, c0, acc);
        }
    }
    // ---- part B: column 255 - q ----
    {
        const int u0 = (v0 > iterA) ? (v0 - iterA) : 0;
        const int u1 = v1 - iterA;
        if (u1 > u0) {
            const int c = 255 - q;
            const int pB0 = 252 - q;
            const int pbeg = pB0 + u0;
            const int pend = pB0 + u1 - 1;
            const int pstart = (u0 == 0) ? pbeg : ((pbeg - 2 > 0) ? pbeg - 2 : 0);
            const int ef = (pbeg > 1) ? pbeg : 1;
            const bool vm = (c >= 1);
            const ps_t csm = vm ? scs[c - 1] : 0ULL;
            const ps_t cs0v = scs[c];
            const ps_t csp = (c <= 254) ? scs[c + 1] : 0ULL;
            if (edge)
                run_colp<true >(c, pstart, pbeg, pend, ef, u0 == 0, vm,
                                csm, cs0v, csp, srs, sW, b2v, c0, acc);
            else
                run_colp<false>(c, pstart, pbeg, pend, ef, u0 == 0, vm,
                                csm, cs0v, csp, srs, sW, b2v, c0, acc);
        }
    }

    // reduce acc across lanes, then across the 4 warps
#pragma unroll
    for (int k = 0; k < 4; ++k) {
#pragma unroll
        for (int o = 16; o; o >>= 1)
            acc[k] = add2(acc[k], __shfl_xor_sync(0xffffffffu, acc[k], o));
    }
    if (lane == 0) {
#pragma unroll
        for (int k = 0; k < 4; ++k) sred[w][k] = acc[k];
    }
    __syncthreads();
    if (t < 4) {
        ps_t sv = add2(add2(sred[0][t], sred[1][t]), add2(sred[2][t], sred[3][t]));
        float lo, hi; up2(sv, lo, hi);
        g_part[bid * 4 + t] = lo + hi;
    }

    // ------- last-block final reduction + fc2 -------
    __threadfence();
    __syncthreads();
    if (t == 0) {
        unsigned int o = atomicAdd(&g_ctr, 1u);
        lastf = (o == (unsigned)(NBLK - 1)) ? 1 : 0;
    }
    __syncthreads();
    if (lastf) {
        float sv = 0.f;
        for (int i = lane; i < NBLK; i += 32) sv += g_part[i * 4 + w];
#pragma unroll
        for (int o = 16; o; o >>= 1) sv += __shfl_xor_sync(0xffffffffu, sv, o);
        __shared__ float fsh[4];
        if (lane == 0) fsh[w] = sv;
        __syncthreads();
        if (t == 0) {
            float h0 = fmaxf(fsh[0] + fc1b[0], 0.f);
            float h1 = fmaxf(fsh[1] + fc1b[1], 0.f);
            float h2 = fmaxf(fsh[2] + fc1b[2], 0.f);
            float h3 = fmaxf(fsh[3] + fc1b[3], 0.f);
            out[0] = fc2w[0] * h0 + fc2w[1] * h1 + fc2w[2] * h2 + fc2w[3] * h3 + fc2b[0];
            out[1] = fc2w[4] * h0 + fc2w[5] * h1 + fc2w[6] * h2 + fc2w[7] * h3 + fc2b[1];
            g_ctr = 0;   // reset for next launch/replay
        }
    }
}

// ---------------------------------------------------------------------------
extern "C" void kernel_launch(void* const* d_in, const int* in_sizes, int n_in,
                              void* d_out, int out_size) {
    const float* x    = (const float*)d_in[0];
    const float* w1   = (const float*)d_in[1];
    const float* b1   = (const float*)d_in[2];
    const float* w2   = (const float*)d_in[3];
    const float* b2   = (const float*)d_in[4];
    const float* fc1w = (const float*)d_in[5];
    const float* fc1b = (const float*)d_in[6];
    const float* fc2w = (const float*)d_in[7];
    const float* fc2b = (const float*)d_in[8];

    ksums<<<4 * NB, 256>>>(x, w1, b1, w2, b2);

    void* gp = nullptr;
    cudaGetSymbolAddress(&gp, g_packv);
    cudaMemcpyToSymbolAsync(c_w1p, gp, 5 * sizeof(ulonglong2), 0,
                            cudaMemcpyDeviceToDevice, 0);
    cudaMemcpyToSymbolAsync(c_b1p, (char*)gp + 5 * sizeof(ulonglong2),
                            5 * sizeof(ulonglong2), 0, cudaMemcpyDeviceToDevice, 0);
    cudaMemcpyToSymbolAsync(c_w2p, (char*)gp + 10 * sizeof(ulonglong2),
                            45 * sizeof(ulonglong2), 0, cudaMemcpyDeviceToDevice, 0);
    cudaMemcpyToSymbolAsync(c_b2p, (char*)gp + 55 * sizeof(ulonglong2),
                            sizeof(ps_t), 0, cudaMemcpyDeviceToDevice, 0);

    kband<<<NBLK, 128>>>(fc1w, fc1b, fc2w, fc2b, (float*)d_out);
}